// round 10
// baseline (speedup 1.0000x reference)
#include <cuda_runtime.h>
#include <cuda_fp16.h>
#include <cstdint>

#define NN 50000
#define NE 800000
#define DIM 128
#define NO 384   /* 3*HIDDEN */

// ---------------- scratch (device globals: allocation-free) ----------------
__device__ float g_aggf[(size_t)NN * DIM];
__device__ float g_aggh[(size_t)NN * DIM];
__device__ __half g_C1[(size_t)NN * NO];     // fp16 intermediates
__device__ __half g_C2[(size_t)NN * NO];
__device__ __half g_f16[(size_t)NN * DIM];   // fp16(nsrc * feat)
__device__ __half g_h16[(size_t)NN * DIM];   // fp16(nsrc * hx)
__device__ __half g_Bih[NO * DIM];   // Wi^T fp16  [n][k]
__device__ __half g_Bhh[NO * DIM];   // Wh^T fp16
__device__ float g_nsrc[NN];
__device__ float g_ndst[NN];
__device__ int   g_degout[NN];
__device__ int   g_degin[NN];
__device__ int   g_off[NN + 1];
__device__ int   g_cur[NN];
__device__ int   g_csrc[NE];
__device__ int   g_cdst[NE];

__device__ __forceinline__ uint32_t smem_u32(const void* p) {
    uint32_t a;
    asm("{ .reg .u64 t; cvta.to.shared.u64 t, %1; cvt.u32.u64 %0, t; }" : "=r"(a) : "l"(p));
    return a;
}

// ---------------- kernel 1: zero agg accumulators + degree counters ----------------
__global__ void zero_kernel() {
    int tid = blockIdx.x * blockDim.x + threadIdx.x;
    int nt = gridDim.x * blockDim.x;
    const int total4 = NN * DIM / 4;
    float4 z = make_float4(0.f, 0.f, 0.f, 0.f);
    for (int p = tid; p < total4; p += nt) {
        reinterpret_cast<float4*>(g_aggf)[p] = z;
        reinterpret_cast<float4*>(g_aggh)[p] = z;
    }
    for (int p = tid; p < NN; p += nt) { g_degout[p] = 0; g_degin[p] = 0; }
}

// ---------------- kernel 2: degrees ----------------
__global__ void deg_kernel(const int* __restrict__ src, const int* __restrict__ dst) {
    int e = blockIdx.x * blockDim.x + threadIdx.x;
    if (e < NE) {
        atomicAdd(&g_degout[src[e]], 1);
        atomicAdd(&g_degin[dst[e]], 1);
    }
}

// ---------------- kernel 3: exclusive scan of degin + norms (single block) ----------------
__global__ __launch_bounds__(1024) void scan_kernel() {
    __shared__ int sm[1024];
    int t = threadIdx.x;
    const int CH = 49;                       // 1024*49 = 50176 >= NN
    int base = t * CH;
    int s = 0;
#pragma unroll
    for (int i = 0; i < CH; i++) {
        int idx = base + i;
        s += (idx < NN) ? g_degin[idx] : 0;
    }
    sm[t] = s;
    __syncthreads();
    for (int d = 1; d < 1024; d <<= 1) {
        int v = (t >= d) ? sm[t - d] : 0;
        __syncthreads();
        sm[t] += v;
        __syncthreads();
    }
    int run = (t == 0) ? 0 : sm[t - 1];
#pragma unroll
    for (int i = 0; i < CH; i++) {
        int idx = base + i;
        if (idx < NN) {
            g_off[idx] = run;
            g_cur[idx] = run;
            run += g_degin[idx];
        }
    }
    if (t == 1023) g_off[NN] = run;
    for (int i = t; i < NN; i += 1024) {
        g_nsrc[i] = rsqrtf(fmaxf((float)g_degout[i], 1.f));
        g_ndst[i] = rsqrtf(fmaxf((float)g_degin[i], 1.f));
    }
}

// ---------------- kernel 4: W^T -> fp16 ----------------
__global__ void prepw_kernel(const float* __restrict__ Wi, const float* __restrict__ Wh) {
    int i = blockIdx.x * blockDim.x + threadIdx.x;
    if (i < NO * DIM) {
        int n = i >> 7, k = i & 127;
        g_Bih[i] = __float2half(Wi[k * NO + n]);
        g_Bhh[i] = __float2half(Wh[k * NO + n]);
    }
}

// ---------------- kernel 5: bin edges by dst (CSR, dst-sorted edge list) ----------
__global__ void csr_kernel(const int* __restrict__ src, const int* __restrict__ dst) {
    int e = blockIdx.x * blockDim.x + threadIdx.x;
    if (e < NE) {
        int d = dst[e];
        int pos = atomicAdd(&g_cur[d], 1);
        g_csrc[pos] = src[e];
        g_cdst[pos] = d;
    }
}

// ---------------- kernel 6: feat/hx -> fp16 with nsrc pre-folded ----------------
__global__ __launch_bounds__(256) void conv_kernel(
    const float* __restrict__ feat, const float* __restrict__ hx)
{
    int i = blockIdx.x * blockDim.x + threadIdx.x;   // one float4 per thread
    if (i >= NN * DIM / 4) return;
    int n = i >> 5;                                   // 32 float4 per row
    float ns = g_nsrc[n];
    float4 f = reinterpret_cast<const float4*>(feat)[i];
    float4 h = reinterpret_cast<const float4*>(hx)[i];
    __half2 f01 = __float22half2_rn(make_float2(ns * f.x, ns * f.y));
    __half2 f23 = __float22half2_rn(make_float2(ns * f.z, ns * f.w));
    __half2 h01 = __float22half2_rn(make_float2(ns * h.x, ns * h.y));
    __half2 h23 = __float22half2_rn(make_float2(ns * h.z, ns * h.w));
    reinterpret_cast<uint2*>(g_f16)[i] =
        make_uint2(*reinterpret_cast<uint32_t*>(&f01), *reinterpret_cast<uint32_t*>(&f23));
    reinterpret_cast<uint2*>(g_h16)[i] =
        make_uint2(*reinterpret_cast<uint32_t*>(&h01), *reinterpret_cast<uint32_t*>(&h23));
}

// ---------------- kernel 7: edge-balanced aggregation (16 edges / warp) -----------
__device__ __forceinline__ void acc_pair(uint2 vf, uint2 vh, float4& af, float4& ah) {
    float2 a = __half22float2(*reinterpret_cast<__half2*>(&vf.x));
    float2 b = __half22float2(*reinterpret_cast<__half2*>(&vf.y));
    af.x += a.x; af.y += a.y; af.z += b.x; af.w += b.y;
    a = __half22float2(*reinterpret_cast<__half2*>(&vh.x));
    b = __half22float2(*reinterpret_cast<__half2*>(&vh.y));
    ah.x += a.x; ah.y += a.y; ah.z += b.x; ah.w += b.y;
}

__device__ __forceinline__ void flushv(int d, int lane, const float4& af, const float4& ah) {
    unsigned long long pf = (unsigned long long)__cvta_generic_to_global(
        g_aggf + (size_t)d * DIM + lane * 4);
    unsigned long long ph = (unsigned long long)__cvta_generic_to_global(
        g_aggh + (size_t)d * DIM + lane * 4);
    asm volatile("red.global.add.v4.f32 [%0], {%1,%2,%3,%4};"
                 :: "l"(pf), "f"(af.x), "f"(af.y), "f"(af.z), "f"(af.w) : "memory");
    asm volatile("red.global.add.v4.f32 [%0], {%1,%2,%3,%4};"
                 :: "l"(ph), "f"(ah.x), "f"(ah.y), "f"(ah.z), "f"(ah.w) : "memory");
}

__global__ __launch_bounds__(256) void agg_kernel() {
    const int CHUNK = 16;                       // NE % 16 == 0
    int w = (blockIdx.x * blockDim.x + threadIdx.x) >> 5;
    int lane = threadIdx.x & 31;
    int e0 = w * CHUNK;
    if (e0 >= NE) return;
    const uint2* f2 = reinterpret_cast<const uint2*>(g_f16);
    const uint2* h2 = reinterpret_cast<const uint2*>(g_h16);
    float4 af = make_float4(0.f, 0.f, 0.f, 0.f);
    float4 ah = make_float4(0.f, 0.f, 0.f, 0.f);
    int curd = __ldg(g_cdst + e0);
#pragma unroll
    for (int base = 0; base < CHUNK; base += 4) {
        int s[4], d[4];
        uint2 vf[4], vh[4];
#pragma unroll
        for (int j = 0; j < 4; j++) {
            s[j] = __ldg(g_csrc + e0 + base + j);
            d[j] = __ldg(g_cdst + e0 + base + j);
        }
#pragma unroll
        for (int j = 0; j < 4; j++) {
            vf[j] = f2[s[j] * 32 + lane];
            vh[j] = h2[s[j] * 32 + lane];
        }
#pragma unroll
        for (int j = 0; j < 4; j++) {
            if (d[j] != curd) {
                flushv(curd, lane, af, ah);
                af = make_float4(0.f, 0.f, 0.f, 0.f);
                ah = make_float4(0.f, 0.f, 0.f, 0.f);
                curd = d[j];
            }
            acc_pair(vf[j], vh[j], af, ah);
        }
    }
    flushv(curd, lane, af, ah);
}

// ---------------- kernel 8: mma.sync fp16 2-pass split GEMM ----------------
// CTA tile 128(M) x 128(N), occupancy 2, warp tile 64x32 (2x4 warps).
// A = Ah + Al (fp16 hi/lo from fp32 agg with ndst folded), B fp16, C stored fp16.
#define PITCH 136                         /* fp16 per smem row (272B) */
#define S_AH 0
#define S_AL (128 * PITCH * 2)            /* 34816 */
#define S_B  (2 * 128 * PITCH * 2)        /* 69632 */
#define GEMM_SMEM (S_B + 128 * PITCH * 2) /* 104448; x2 CTAs <= 227KB */

__global__ __launch_bounds__(256, 2) void gemm_kernel() {
    extern __shared__ char smem[];
    uint32_t sb = smem_u32(smem);
    int tid = threadIdx.x, lane = tid & 31, wid = tid >> 5;
    int warp_m = wid & 1, warp_n = wid >> 1;   // 2 x 4 warps, warp tile 64 x 32
    int m0 = blockIdx.x * 128, n0 = blockIdx.y * 128;
    const float* Agg     = blockIdx.z ? g_aggh : g_aggf;
    const __half* B      = blockIdx.z ? g_Bhh  : g_Bih;
    __half* C            = blockIdx.z ? g_C2   : g_C1;

    // ---- B tile via cp.async (128 rows x 16 uint4) ----
    {
        const uint4* BU = reinterpret_cast<const uint4*>(B);
#pragma unroll
        for (int i = 0; i < 8; i++) {
            int p = tid + i * 256;               // 2048
            int r = p >> 4, q = p & 15;
            uint32_t doff = (uint32_t)(r * PITCH * 2 + q * 16);
            const uint4* g = BU + (n0 + r) * 16 + q;
            asm volatile("cp.async.cg.shared.global [%0], [%1], 16;"
                         :: "r"(sb + S_B + doff), "l"(g) : "memory");
        }
        asm volatile("cp.async.commit_group;" ::: "memory");
    }

    // ---- A tiles: fp32 -> (hi, lo) fp16 (128 rows x 32 float4) ----
#pragma unroll
    for (int i = 0; i < 16; i++) {
        int p = tid + i * 256;                   // 4096 float4
        int r = p >> 5, q = p & 31;
        int gm = m0 + r;
        float4 v = make_float4(0.f, 0.f, 0.f, 0.f);
        if (gm < NN) {
            float nd = g_ndst[gm];
            v = reinterpret_cast<const float4*>(Agg)[gm * 32 + q];
            v.x *= nd; v.y *= nd; v.z *= nd; v.w *= nd;
        }
        __half2 h0 = __float22half2_rn(make_float2(v.x, v.y));
        __half2 h1 = __float22half2_rn(make_float2(v.z, v.w));
        float2 h0f = __half22float2(h0);
        float2 h1f = __half22float2(h1);
        __half2 l0 = __float22half2_rn(make_float2(v.x - h0f.x, v.y - h0f.y));
        __half2 l1 = __float22half2_rn(make_float2(v.z - h1f.x, v.w - h1f.y));
        uint32_t off = (uint32_t)(r * PITCH + q * 4) * 2;
        *reinterpret_cast<uint2*>(smem + S_AH + off) =
            make_uint2(*reinterpret_cast<uint32_t*>(&h0), *reinterpret_cast<uint32_t*>(&h1));
        *reinterpret_cast<uint2*>(smem + S_AL + off) =
            make_uint2(*reinterpret_cast<uint32_t*>(&l0), *reinterpret_cast<uint32_t*>(&l1));
    }
    asm volatile("cp.async.wait_group 0;" ::: "memory");
    __syncthreads();

    float acc[4][4][4];
#pragma unroll
    for (int mi = 0; mi < 4; mi++)
#pragma unroll
        for (int ni = 0; ni < 4; ni++)
#pragma unroll
            for (int j = 0; j < 4; j++) acc[mi][ni][j] = 0.f;

    int a_row = (lane & 7) + ((lane >> 3) & 1) * 8;
    int a_kof = (lane >> 4) * 8;
    int b_row = (lane & 7) + (lane >> 4) * 8;
    int b_kof = ((lane >> 3) & 1) * 8;

#pragma unroll
    for (int pass = 0; pass < 2; pass++) {
        uint32_t sA = sb + (pass ? S_AL : S_AH);
        uint32_t sB = sb + S_B;
#pragma unroll
        for (int ks = 0; ks < 8; ks++) {
            int k0 = ks * 16;
            uint32_t a[4][4], b[4][2];
#pragma unroll
            for (int mi = 0; mi < 4; mi++) {
                uint32_t addr = sA + ((warp_m * 64 + mi * 16 + a_row) * PITCH + k0 + a_kof) * 2;
                asm volatile("ldmatrix.sync.aligned.m8n8.x4.shared.b16 {%0,%1,%2,%3}, [%4];"
                             : "=r"(a[mi][0]), "=r"(a[mi][1]), "=r"(a[mi][2]), "=r"(a[mi][3])
                             : "r"(addr));
            }
#pragma unroll
            for (int nh = 0; nh < 2; nh++) {
                uint32_t addr = sB + ((warp_n * 32 + nh * 16 + b_row) * PITCH + k0 + b_kof) * 2;
                uint32_t r0, r1, r2, r3;
                asm volatile("ldmatrix.sync.aligned.m8n8.x4.shared.b16 {%0,%1,%2,%3}, [%4];"
                             : "=r"(r0), "=r"(r1), "=r"(r2), "=r"(r3)
                             : "r"(addr));
                b[nh * 2][0] = r0; b[nh * 2][1] = r1;
                b[nh * 2 + 1][0] = r2; b[nh * 2 + 1][1] = r3;
            }
#pragma unroll
            for (int mi = 0; mi < 4; mi++)
#pragma unroll
                for (int ni = 0; ni < 4; ni++) {
                    asm volatile(
                        "mma.sync.aligned.m16n8k16.row.col.f32.f16.f16.f32 "
                        "{%0,%1,%2,%3}, {%4,%5,%6,%7}, {%8,%9}, {%0,%1,%2,%3};"
                        : "+f"(acc[mi][ni][0]), "+f"(acc[mi][ni][1]),
                          "+f"(acc[mi][ni][2]), "+f"(acc[mi][ni][3])
                        : "r"(a[mi][0]), "r"(a[mi][1]), "r"(a[mi][2]), "r"(a[mi][3]),
                          "r"(b[ni][0]), "r"(b[ni][1]));
                }
        }
    }

    // ---- epilogue: fp16 stores ----
#pragma unroll
    for (int mi = 0; mi < 4; mi++) {
        int row = m0 + warp_m * 64 + mi * 16 + (lane >> 2);
#pragma unroll
        for (int ni = 0; ni < 4; ni++) {
            int col = n0 + warp_n * 32 + ni * 8 + (lane & 3) * 2;
            if (row < NN) {
                *reinterpret_cast<__half2*>(C + (size_t)row * NO + col) =
                    __float22half2_rn(make_float2(acc[mi][ni][0], acc[mi][ni][1]));
            }
            if (row + 8 < NN) {
                *reinterpret_cast<__half2*>(C + (size_t)(row + 8) * NO + col) =
                    __float22half2_rn(make_float2(acc[mi][ni][2], acc[mi][ni][3]));
            }
        }
    }
}

// ---------------- kernel 9: GRU gating (fp16 C, 2 channels/thread) ----------------
__global__ __launch_bounds__(256) void gru_kernel(
    const float* __restrict__ hx, const float* __restrict__ bi,
    const float* __restrict__ bh, float* __restrict__ out)
{
    int idx = blockIdx.x * blockDim.x + threadIdx.x;   // NN * 64 threads
    if (idx >= NN * 64) return;
    int n = idx >> 6, ch = (idx & 63);                 // half2 index within 128 chans
    const __half2* c1 = reinterpret_cast<const __half2*>(g_C1 + (size_t)n * NO);
    const __half2* c2 = reinterpret_cast<const __half2*>(g_C2 + (size_t)n * NO);
    int c = ch * 2;
    float2 c1r = __half22float2(c1[ch]);
    float2 c1z = __half22float2(c1[ch + 64]);
    float2 c1n = __half22float2(c1[ch + 128]);
    float2 c2r = __half22float2(c2[ch]);
    float2 c2z = __half22float2(c2[ch + 64]);
    float2 c2n = __half22float2(c2[ch + 128]);
    float2 bir = *reinterpret_cast<const float2*>(bi + c);
    float2 biz = *reinterpret_cast<const float2*>(bi + c + 128);
    float2 bin = *reinterpret_cast<const float2*>(bi + c + 256);
    float2 bhr = *reinterpret_cast<const float2*>(bh + c);
    float2 bhz = *reinterpret_cast<const float2*>(bh + c + 128);
    float2 bhn = *reinterpret_cast<const float2*>(bh + c + 256);
    float2 hv = *reinterpret_cast<const float2*>(hx + (size_t)n * DIM + c);
    float2 o;
    {
        float r = 1.f / (1.f + __expf(-(c1r.x + c2r.x + bir.x + bhr.x)));
        float z = 1.f / (1.f + __expf(-(c1z.x + c2z.x + biz.x + bhz.x)));
        float nn = tanhf(c1n.x + bin.x + r * (c2n.x + bhn.x));
        o.x = (1.f - z) * nn + z * hv.x;
    }
    {
        float r = 1.f / (1.f + __expf(-(c1r.y + c2r.y + bir.y + bhr.y)));
        float z = 1.f / (1.f + __expf(-(c1z.y + c2z.y + biz.y + bhz.y)));
        float nn = tanhf(c1n.y + bin.y + r * (c2n.y + bhn.y));
        o.y = (1.f - z) * nn + z * hv.y;
    }
    *reinterpret_cast<float2*>(out + (size_t)n * DIM + c) = o;
}

// ---------------- launch ----------------
extern "C" void kernel_launch(void* const* d_in, const int* in_sizes, int n_in,
                              void* d_out, int out_size)
{
    const float* feat = (const float*)d_in[0];
    const float* hx   = (const float*)d_in[1];
    const float* Wi   = (const float*)d_in[2];
    const float* bi   = (const float*)d_in[3];
    const float* Wh   = (const float*)d_in[4];
    const float* bh   = (const float*)d_in[5];
    const int*   src  = (const int*)d_in[6];
    const int*   dst  = (const int*)d_in[7];
    float* out = (float*)d_out;

    cudaFuncSetAttribute(gemm_kernel, cudaFuncAttributeMaxDynamicSharedMemorySize, GEMM_SMEM);

    zero_kernel<<<1024, 256>>>();
    deg_kernel<<<(NE + 255) / 256, 256>>>(src, dst);
    scan_kernel<<<1, 1024>>>();
    prepw_kernel<<<(NO * DIM + 255) / 256, 256>>>(Wi, Wh);
    csr_kernel<<<(NE + 255) / 256, 256>>>(src, dst);
    conv_kernel<<<(NN * DIM / 4 + 255) / 256, 256>>>(feat, hx);
    agg_kernel<<<(NE / 16 * 32 + 255) / 256, 256>>>();
    gemm_kernel<<<dim3((NN + 127) / 128, NO / 128, 2), 256, GEMM_SMEM>>>();
    gru_kernel<<<(NN * 64 + 255) / 256, 256>>>(hx, bi, bh, out);
}

// round 11
// speedup vs baseline: 1.0952x; 1.0952x over previous
#include <cuda_runtime.h>
#include <cuda_fp16.h>
#include <cstdint>

#define NN 50000
#define NE 800000
#define DIM 128
#define NO 384   /* 3*HIDDEN */

// ---------------- scratch (device globals: allocation-free) ----------------
__device__ float g_aggf[(size_t)NN * DIM];
__device__ float g_aggh[(size_t)NN * DIM];
__device__ __half g_C1[(size_t)NN * NO];     // fp16 intermediates
__device__ __half g_C2[(size_t)NN * NO];
__device__ __half g_f16[(size_t)NN * DIM];   // fp16(nsrc * feat)
__device__ __half g_h16[(size_t)NN * DIM];   // fp16(nsrc * hx)
__device__ __half g_Bih[NO * DIM];   // Wi^T fp16  [n][k]
__device__ __half g_Bhh[NO * DIM];   // Wh^T fp16
__device__ float g_nsrc[NN];
__device__ float g_ndst[NN];
__device__ int   g_degout[NN];
__device__ int   g_degin[NN];
__device__ int   g_off[NN + 1];
__device__ int   g_cur[NN];
__device__ int   g_csrc[NE];

__device__ __forceinline__ uint32_t smem_u32(const void* p) {
    uint32_t a;
    asm("{ .reg .u64 t; cvta.to.shared.u64 t, %1; cvt.u32.u64 %0, t; }" : "=r"(a) : "l"(p));
    return a;
}

// ---------------- kernel 1: zero degree counters ----------------
__global__ void zero_kernel() {
    int i = blockIdx.x * blockDim.x + threadIdx.x;
    if (i < NN) { g_degout[i] = 0; g_degin[i] = 0; }
}

// ---------------- kernel 2: degrees ----------------
__global__ void deg_kernel(const int* __restrict__ src, const int* __restrict__ dst) {
    int e = blockIdx.x * blockDim.x + threadIdx.x;
    if (e < NE) {
        atomicAdd(&g_degout[src[e]], 1);
        atomicAdd(&g_degin[dst[e]], 1);
    }
}

// ---------------- kernel 3: exclusive scan of degin + norms (single block) ----------------
__global__ __launch_bounds__(1024) void scan_kernel() {
    __shared__ int sm[1024];
    int t = threadIdx.x;
    const int CH = 49;                       // 1024*49 = 50176 >= NN
    int base = t * CH;
    int s = 0;
#pragma unroll
    for (int i = 0; i < CH; i++) {
        int idx = base + i;
        s += (idx < NN) ? g_degin[idx] : 0;
    }
    sm[t] = s;
    __syncthreads();
    for (int d = 1; d < 1024; d <<= 1) {
        int v = (t >= d) ? sm[t - d] : 0;
        __syncthreads();
        sm[t] += v;
        __syncthreads();
    }
    int run = (t == 0) ? 0 : sm[t - 1];
#pragma unroll
    for (int i = 0; i < CH; i++) {
        int idx = base + i;
        if (idx < NN) {
            g_off[idx] = run;
            g_cur[idx] = run;
            run += g_degin[idx];
        }
    }
    if (t == 1023) g_off[NN] = run;
    for (int i = t; i < NN; i += 1024) {
        g_nsrc[i] = rsqrtf(fmaxf((float)g_degout[i], 1.f));
        g_ndst[i] = rsqrtf(fmaxf((float)g_degin[i], 1.f));
    }
}

// ---------------- kernel 4: W^T -> fp16 ----------------
__global__ void prepw_kernel(const float* __restrict__ Wi, const float* __restrict__ Wh) {
    int i = blockIdx.x * blockDim.x + threadIdx.x;
    if (i < NO * DIM) {
        int n = i >> 7, k = i & 127;
        g_Bih[i] = __float2half(Wi[k * NO + n]);
        g_Bhh[i] = __float2half(Wh[k * NO + n]);
    }
}

// ---------------- kernel 5: bin edges by dst (CSR) ----------------
__global__ void csr_kernel(const int* __restrict__ src, const int* __restrict__ dst) {
    int e = blockIdx.x * blockDim.x + threadIdx.x;
    if (e < NE) {
        int d = dst[e];
        int pos = atomicAdd(&g_cur[d], 1);
        g_csrc[pos] = src[e];
    }
}

// ---------------- kernel 6: feat/hx -> fp16 with nsrc pre-folded ----------------
__global__ __launch_bounds__(256) void conv_kernel(
    const float* __restrict__ feat, const float* __restrict__ hx)
{
    int i = blockIdx.x * blockDim.x + threadIdx.x;   // one float4 per thread
    if (i >= NN * DIM / 4) return;
    int n = i >> 5;                                   // 32 float4 per row
    float ns = g_nsrc[n];
    float4 f = reinterpret_cast<const float4*>(feat)[i];
    float4 h = reinterpret_cast<const float4*>(hx)[i];
    __half2 f01 = __float22half2_rn(make_float2(ns * f.x, ns * f.y));
    __half2 f23 = __float22half2_rn(make_float2(ns * f.z, ns * f.w));
    __half2 h01 = __float22half2_rn(make_float2(ns * h.x, ns * h.y));
    __half2 h23 = __float22half2_rn(make_float2(ns * h.z, ns * h.w));
    reinterpret_cast<uint2*>(g_f16)[i] =
        make_uint2(*reinterpret_cast<uint32_t*>(&f01), *reinterpret_cast<uint32_t*>(&f23));
    reinterpret_cast<uint2*>(g_h16)[i] =
        make_uint2(*reinterpret_cast<uint32_t*>(&h01), *reinterpret_cast<uint32_t*>(&h23));
}

// ---------------- kernel 7: per-node aggregation (warp per dst, 4-edge unroll) ----
__device__ __forceinline__ void acc_pair(uint2 vf, uint2 vh, float4& af, float4& ah) {
    float2 a = __half22float2(*reinterpret_cast<__half2*>(&vf.x));
    float2 b = __half22float2(*reinterpret_cast<__half2*>(&vf.y));
    af.x += a.x; af.y += a.y; af.z += b.x; af.w += b.y;
    a = __half22float2(*reinterpret_cast<__half2*>(&vh.x));
    b = __half22float2(*reinterpret_cast<__half2*>(&vh.y));
    ah.x += a.x; ah.y += a.y; ah.z += b.x; ah.w += b.y;
}

__global__ __launch_bounds__(256) void agg_kernel() {
    int w = (blockIdx.x * blockDim.x + threadIdx.x) >> 5;
    int lane = threadIdx.x & 31;
    if (w >= NN) return;
    int beg = g_off[w], end = g_off[w + 1];
    const uint2* f2 = reinterpret_cast<const uint2*>(g_f16);
    const uint2* h2 = reinterpret_cast<const uint2*>(g_h16);
    float4 af = make_float4(0.f, 0.f, 0.f, 0.f);
    float4 ah = make_float4(0.f, 0.f, 0.f, 0.f);
    int p = beg;
    for (; p + 3 < end; p += 4) {
        int s0 = __ldg(g_csrc + p);
        int s1 = __ldg(g_csrc + p + 1);
        int s2 = __ldg(g_csrc + p + 2);
        int s3 = __ldg(g_csrc + p + 3);
        uint2 vf0 = f2[s0 * 32 + lane];
        uint2 vh0 = h2[s0 * 32 + lane];
        uint2 vf1 = f2[s1 * 32 + lane];
        uint2 vh1 = h2[s1 * 32 + lane];
        uint2 vf2 = f2[s2 * 32 + lane];
        uint2 vh2 = h2[s2 * 32 + lane];
        uint2 vf3 = f2[s3 * 32 + lane];
        uint2 vh3 = h2[s3 * 32 + lane];
        acc_pair(vf0, vh0, af, ah);
        acc_pair(vf1, vh1, af, ah);
        acc_pair(vf2, vh2, af, ah);
        acc_pair(vf3, vh3, af, ah);
    }
    for (; p < end; p++) {
        int s = __ldg(g_csrc + p);
        uint2 vf = f2[s * 32 + lane];
        uint2 vh = h2[s * 32 + lane];
        acc_pair(vf, vh, af, ah);
    }
    reinterpret_cast<float4*>(g_aggf)[w * 32 + lane] = af;
    reinterpret_cast<float4*>(g_aggh)[w * 32 + lane] = ah;
}

// ---------------- kernel 8: mma.sync fp16 single-pass GEMM ----------------
// CTA tile 128(M) x 128(N), occupancy 3, warp tile 64x32 (2x4 warps).
// A fp16 (converted in-kernel from fp32 agg, ndst folded), B fp16, C fp16.
#define PITCH 136                         /* fp16 per smem row (272B) */
#define S_A  0
#define S_B  (128 * PITCH * 2)            /* 34816 */
#define GEMM_SMEM (S_B + 128 * PITCH * 2) /* 69632; x3 CTAs <= 227KB */

__global__ __launch_bounds__(256, 3) void gemm_kernel() {
    extern __shared__ char smem[];
    uint32_t sb = smem_u32(smem);
    int tid = threadIdx.x, lane = tid & 31, wid = tid >> 5;
    int warp_m = wid & 1, warp_n = wid >> 1;   // 2 x 4 warps, warp tile 64 x 32
    int m0 = blockIdx.x * 128, n0 = blockIdx.y * 128;
    const float* Agg     = blockIdx.z ? g_aggh : g_aggf;
    const __half* B      = blockIdx.z ? g_Bhh  : g_Bih;
    __half* C            = blockIdx.z ? g_C2   : g_C1;

    // ---- B tile via cp.async (128 rows x 16 uint4) ----
    {
        const uint4* BU = reinterpret_cast<const uint4*>(B);
#pragma unroll
        for (int i = 0; i < 8; i++) {
            int p = tid + i * 256;               // 2048
            int r = p >> 4, q = p & 15;
            uint32_t doff = (uint32_t)(r * PITCH * 2 + q * 16);
            const uint4* g = BU + (n0 + r) * 16 + q;
            asm volatile("cp.async.cg.shared.global [%0], [%1], 16;"
                         :: "r"(sb + S_B + doff), "l"(g) : "memory");
        }
        asm volatile("cp.async.commit_group;" ::: "memory");
    }

    // ---- A tile: fp32 -> fp16 (128 rows x 32 float4) ----
#pragma unroll
    for (int i = 0; i < 16; i++) {
        int p = tid + i * 256;                   // 4096 float4
        int r = p >> 5, q = p & 31;
        int gm = m0 + r;
        float4 v = make_float4(0.f, 0.f, 0.f, 0.f);
        if (gm < NN) {
            float nd = g_ndst[gm];
            v = reinterpret_cast<const float4*>(Agg)[gm * 32 + q];
            v.x *= nd; v.y *= nd; v.z *= nd; v.w *= nd;
        }
        __half2 h0 = __float22half2_rn(make_float2(v.x, v.y));
        __half2 h1 = __float22half2_rn(make_float2(v.z, v.w));
        uint32_t off = (uint32_t)(r * PITCH + q * 4) * 2;
        *reinterpret_cast<uint2*>(smem + S_A + off) =
            make_uint2(*reinterpret_cast<uint32_t*>(&h0), *reinterpret_cast<uint32_t*>(&h1));
    }
    asm volatile("cp.async.wait_group 0;" ::: "memory");
    __syncthreads();

    float acc[4][4][4];
#pragma unroll
    for (int mi = 0; mi < 4; mi++)
#pragma unroll
        for (int ni = 0; ni < 4; ni++)
#pragma unroll
            for (int j = 0; j < 4; j++) acc[mi][ni][j] = 0.f;

    int a_row = (lane & 7) + ((lane >> 3) & 1) * 8;
    int a_kof = (lane >> 4) * 8;
    int b_row = (lane & 7) + (lane >> 4) * 8;
    int b_kof = ((lane >> 3) & 1) * 8;

    uint32_t sA = sb + S_A;
    uint32_t sB = sb + S_B;
#pragma unroll
    for (int ks = 0; ks < 8; ks++) {
        int k0 = ks * 16;
        uint32_t a[4][4], b[4][2];
#pragma unroll
        for (int mi = 0; mi < 4; mi++) {
            uint32_t addr = sA + ((warp_m * 64 + mi * 16 + a_row) * PITCH + k0 + a_kof) * 2;
            asm volatile("ldmatrix.sync.aligned.m8n8.x4.shared.b16 {%0,%1,%2,%3}, [%4];"
                         : "=r"(a[mi][0]), "=r"(a[mi][1]), "=r"(a[mi][2]), "=r"(a[mi][3])
                         : "r"(addr));
        }
#pragma unroll
        for (int nh = 0; nh < 2; nh++) {
            uint32_t addr = sB + ((warp_n * 32 + nh * 16 + b_row) * PITCH + k0 + b_kof) * 2;
            uint32_t r0, r1, r2, r3;
            asm volatile("ldmatrix.sync.aligned.m8n8.x4.shared.b16 {%0,%1,%2,%3}, [%4];"
                         : "=r"(r0), "=r"(r1), "=r"(r2), "=r"(r3)
                         : "r"(addr));
            b[nh * 2][0] = r0; b[nh * 2][1] = r1;
            b[nh * 2 + 1][0] = r2; b[nh * 2 + 1][1] = r3;
        }
#pragma unroll
        for (int mi = 0; mi < 4; mi++)
#pragma unroll
            for (int ni = 0; ni < 4; ni++) {
                asm volatile(
                    "mma.sync.aligned.m16n8k16.row.col.f32.f16.f16.f32 "
                    "{%0,%1,%2,%3}, {%4,%5,%6,%7}, {%8,%9}, {%0,%1,%2,%3};"
                    : "+f"(acc[mi][ni][0]), "+f"(acc[mi][ni][1]),
                      "+f"(acc[mi][ni][2]), "+f"(acc[mi][ni][3])
                    : "r"(a[mi][0]), "r"(a[mi][1]), "r"(a[mi][2]), "r"(a[mi][3]),
                      "r"(b[ni][0]), "r"(b[ni][1]));
            }
    }

    // ---- epilogue: fp16 stores ----
#pragma unroll
    for (int mi = 0; mi < 4; mi++) {
        int row = m0 + warp_m * 64 + mi * 16 + (lane >> 2);
#pragma unroll
        for (int ni = 0; ni < 4; ni++) {
            int col = n0 + warp_n * 32 + ni * 8 + (lane & 3) * 2;
            if (row < NN) {
                *reinterpret_cast<__half2*>(C + (size_t)row * NO + col) =
                    __float22half2_rn(make_float2(acc[mi][ni][0], acc[mi][ni][1]));
            }
            if (row + 8 < NN) {
                *reinterpret_cast<__half2*>(C + (size_t)(row + 8) * NO + col) =
                    __float22half2_rn(make_float2(acc[mi][ni][2], acc[mi][ni][3]));
            }
        }
    }
}

// ---------------- kernel 9: GRU gating (fp16 C, 2 channels/thread) ----------------
__global__ __launch_bounds__(256) void gru_kernel(
    const float* __restrict__ hx, const float* __restrict__ bi,
    const float* __restrict__ bh, float* __restrict__ out)
{
    int idx = blockIdx.x * blockDim.x + threadIdx.x;   // NN * 64 threads
    if (idx >= NN * 64) return;
    int n = idx >> 6, ch = (idx & 63);                 // half2 index within 128 chans
    const __half2* c1 = reinterpret_cast<const __half2*>(g_C1 + (size_t)n * NO);
    const __half2* c2 = reinterpret_cast<const __half2*>(g_C2 + (size_t)n * NO);
    int c = ch * 2;
    float2 c1r = __half22float2(c1[ch]);
    float2 c1z = __half22float2(c1[ch + 64]);
    float2 c1n = __half22float2(c1[ch + 128]);
    float2 c2r = __half22float2(c2[ch]);
    float2 c2z = __half22float2(c2[ch + 64]);
    float2 c2n = __half22float2(c2[ch + 128]);
    float2 bir = *reinterpret_cast<const float2*>(bi + c);
    float2 biz = *reinterpret_cast<const float2*>(bi + c + 128);
    float2 bin = *reinterpret_cast<const float2*>(bi + c + 256);
    float2 bhr = *reinterpret_cast<const float2*>(bh + c);
    float2 bhz = *reinterpret_cast<const float2*>(bh + c + 128);
    float2 bhn = *reinterpret_cast<const float2*>(bh + c + 256);
    float2 hv = *reinterpret_cast<const float2*>(hx + (size_t)n * DIM + c);
    float2 o;
    {
        float r = 1.f / (1.f + __expf(-(c1r.x + c2r.x + bir.x + bhr.x)));
        float z = 1.f / (1.f + __expf(-(c1z.x + c2z.x + biz.x + bhz.x)));
        float nn = tanhf(c1n.x + bin.x + r * (c2n.x + bhn.x));
        o.x = (1.f - z) * nn + z * hv.x;
    }
    {
        float r = 1.f / (1.f + __expf(-(c1r.y + c2r.y + bir.y + bhr.y)));
        float z = 1.f / (1.f + __expf(-(c1z.y + c2z.y + biz.y + bhz.y)));
        float nn = tanhf(c1n.y + bin.y + r * (c2n.y + bhn.y));
        o.y = (1.f - z) * nn + z * hv.y;
    }
    *reinterpret_cast<float2*>(out + (size_t)n * DIM + c) = o;
}

// ---------------- launch ----------------
extern "C" void kernel_launch(void* const* d_in, const int* in_sizes, int n_in,
                              void* d_out, int out_size)
{
    const float* feat = (const float*)d_in[0];
    const float* hx   = (const float*)d_in[1];
    const float* Wi   = (const float*)d_in[2];
    const float* bi   = (const float*)d_in[3];
    const float* Wh   = (const float*)d_in[4];
    const float* bh   = (const float*)d_in[5];
    const int*   src  = (const int*)d_in[6];
    const int*   dst  = (const int*)d_in[7];
    float* out = (float*)d_out;

    cudaFuncSetAttribute(gemm_kernel, cudaFuncAttributeMaxDynamicSharedMemorySize, GEMM_SMEM);

    zero_kernel<<<(NN + 255) / 256, 256>>>();
    deg_kernel<<<(NE + 255) / 256, 256>>>(src, dst);
    scan_kernel<<<1, 1024>>>();
    prepw_kernel<<<(NO * DIM + 255) / 256, 256>>>(Wi, Wh);
    csr_kernel<<<(NE + 255) / 256, 256>>>(src, dst);
    conv_kernel<<<(NN * DIM / 4 + 255) / 256, 256>>>(feat, hx);
    agg_kernel<<<(NN * 32 + 255) / 256, 256>>>();
    gemm_kernel<<<dim3((NN + 127) / 128, NO / 128, 2), 256, GEMM_SMEM>>>();
    gru_kernel<<<(NN * 64 + 255) / 256, 256>>>(hx, bi, bh, out);
}